// round 12
// baseline (speedup 1.0000x reference)
#include <cuda_runtime.h>
#include <cuda_bf16.h>
#include <cuda_fp16.h>
#include <cstdint>

#define NMAX 50000
#define EMAX 800000
#define F_IN 128
#define F_OUT 64
#define TILE_M 128
#define CAP 64                               // per-dst bucket capacity (max deg ~42)
#define WSPLIT_BLKS 32                       // 8192 / 256

// ---- device scratch (no allocations allowed) ----
__device__ __half2 g_hh[NMAX * 32];          // h in half2 (rows of 128 B)
__device__ float g_as[NMAX];                 // h . a1
__device__ float g_ad[NMAX];                 // h . a2
__device__ int   g_cnt[NMAX];                // per-dst cursor / degree
__device__ int   g_eb[NMAX * CAP];           // src buckets (12.8 MB)
__device__ uint4 g_whi4[1024];               // W hi split, bf16 [128][64]
__device__ uint4 g_wlo4[1024];               // W lo split, bf16 [128][64]

// ============================ init: zero counters + W split ============================
__global__ void k_init(const float* __restrict__ W, int N, int zblks) {
    int b = blockIdx.x;
    int t = threadIdx.x;
    if (b < zblks) {
        int i = b * 256 + t;
        if (i < N) g_cnt[i] = 0;
    } else {
        int i = (b - zblks) * 256 + t;       // < 8192
        float w = W[i];
        __nv_bfloat16 hi = __float2bfloat16(w);
        __nv_bfloat16 lo = __float2bfloat16(w - __bfloat162float(hi));
        ((__nv_bfloat16*)g_whi4)[i] = hi;
        ((__nv_bfloat16*)g_wlo4)[i] = lo;
    }
}

// ============================ HMMA GEMM (A direct-from-gmem) + fused alpha ============================
#define PB_B 144
#define SM_B_HI 0
#define SM_B_LO (F_IN * PB_B)
#define SM_TOTAL (2 * F_IN * PB_B)           // 36 KB

__device__ __forceinline__ uint32_t smem_u32(const void* p) {
    uint32_t a;
    asm("{ .reg .u64 t; cvta.to.shared.u64 t, %1; cvt.u32.u64 %0, t; }" : "=r"(a) : "l"(p));
    return a;
}

__device__ __forceinline__ void split2(float a, float b, uint32_t& hi, uint32_t& lo) {
    __nv_bfloat16 ah = __float2bfloat16(a);
    __nv_bfloat16 bh = __float2bfloat16(b);
    __nv_bfloat16 al = __float2bfloat16(a - __bfloat162float(ah));
    __nv_bfloat16 bl = __float2bfloat16(b - __bfloat162float(bh));
    hi = (uint32_t)__bfloat16_as_ushort(ah) | ((uint32_t)__bfloat16_as_ushort(bh) << 16);
    lo = (uint32_t)__bfloat16_as_ushort(al) | ((uint32_t)__bfloat16_as_ushort(bl) << 16);
}

#define LDSM_X4T(r0, r1, r2, r3, addr) \
    asm volatile("ldmatrix.sync.aligned.m8n8.x4.trans.shared.b16 {%0,%1,%2,%3}, [%4];" \
                 : "=r"(r0), "=r"(r1), "=r"(r2), "=r"(r3) : "r"(addr))
#define MMA_BF16(d, a0, a1, a2, a3, b0, b1) \
    asm volatile("mma.sync.aligned.m16n8k16.row.col.f32.bf16.bf16.f32 " \
                 "{%0,%1,%2,%3}, {%4,%5,%6,%7}, {%8,%9}, {%0,%1,%2,%3};" \
                 : "+f"((d)[0]), "+f"((d)[1]), "+f"((d)[2]), "+f"((d)[3]) \
                 : "r"(a0), "r"(a1), "r"(a2), "r"(a3), "r"(b0), "r"(b1))

__global__ void __launch_bounds__(256, 3)
k_gemm_mma(const float* __restrict__ x, const float* __restrict__ att, int N) {
    extern __shared__ char smem[];
    uint32_t sb = smem_u32(smem);
    int tid = threadIdx.x;
    int wid = tid >> 5;
    int lane = tid & 31;
    int row0 = blockIdx.x * TILE_M;

    for (int i = tid; i < 1024; i += 256) {
        int k = i >> 3, c8 = i & 7;
        int off = k * PB_B + c8 * 16;
        *(uint4*)(smem + SM_B_HI + off) = g_whi4[i];
        *(uint4*)(smem + SM_B_LO + off) = g_wlo4[i];
    }
    __syncthreads();

    int lr = lane >> 2;
    int lc = lane & 3;
    int row_a = row0 + 16 * wid + lr;
    int row_b = row_a + 8;
    bool va = row_a < N, vb = row_b < N;
    const float* pa = x + (size_t)row_a * F_IN + lc * 2;
    const float* pb = x + (size_t)row_b * F_IN + lc * 2;

    int mi = lane >> 3;
    int wrow = lane & 7;
    uint32_t boff = (uint32_t)((wrow + (mi & 1) * 8) * PB_B + (mi >> 1) * 16);
    uint32_t bhi_base = sb + SM_B_HI + boff;
    uint32_t blo_base = sb + SM_B_LO + boff;

    float d[8][4];
    #pragma unroll
    for (int i = 0; i < 8; i++)
        #pragma unroll
        for (int j = 0; j < 4; j++) d[i][j] = 0.f;

    #pragma unroll
    for (int ks = 0; ks < 8; ks++) {
        float2 z = make_float2(0.f, 0.f);
        float2 xa0 = va ? *(const float2*)(pa + ks * 16)     : z;
        float2 xa1 = va ? *(const float2*)(pa + ks * 16 + 8) : z;
        float2 xb0 = vb ? *(const float2*)(pb + ks * 16)     : z;
        float2 xb1 = vb ? *(const float2*)(pb + ks * 16 + 8) : z;
        uint32_t ah[4], al[4];
        split2(xa0.x, xa0.y, ah[0], al[0]);
        split2(xb0.x, xb0.y, ah[1], al[1]);
        split2(xa1.x, xa1.y, ah[2], al[2]);
        split2(xb1.x, xb1.y, ah[3], al[3]);

        uint32_t bk = ks * 16 * PB_B;
        #pragma unroll
        for (int np = 0; np < 4; np++) {
            uint32_t h0, h1, h2, h3, l0, l1, l2, l3;
            LDSM_X4T(h0, h1, h2, h3, bhi_base + bk + np * 32);
            LDSM_X4T(l0, l1, l2, l3, blo_base + bk + np * 32);
            MMA_BF16(d[2 * np], ah[0], ah[1], ah[2], ah[3], h0, h1);
            MMA_BF16(d[2 * np], ah[0], ah[1], ah[2], ah[3], l0, l1);
            MMA_BF16(d[2 * np], al[0], al[1], al[2], al[3], h0, h1);
            MMA_BF16(d[2 * np + 1], ah[0], ah[1], ah[2], ah[3], h2, h3);
            MMA_BF16(d[2 * np + 1], ah[0], ah[1], ah[2], ah[3], l2, l3);
            MMA_BF16(d[2 * np + 1], al[0], al[1], al[2], al[3], h2, h3);
        }
    }

    // epilogue: h -> half2 + fused alpha dots
    int g = lane >> 2, tg = lane & 3;
    int ra = row0 + 16 * wid + g;
    int rb = ra + 8;
    float sa = 0.f, da = 0.f, sb_ = 0.f, db = 0.f;
    #pragma unroll
    for (int ng = 0; ng < 8; ng++) {
        int col = ng * 8 + tg * 2;
        float2 A1 = *(const float2*)&att[col];
        float2 A2 = *(const float2*)&att[F_OUT + col];
        sa  += d[ng][0] * A1.x + d[ng][1] * A1.y;
        da  += d[ng][0] * A2.x + d[ng][1] * A2.y;
        sb_ += d[ng][2] * A1.x + d[ng][3] * A1.y;
        db  += d[ng][2] * A2.x + d[ng][3] * A2.y;
        int hidx = ng * 4 + tg;
        if (ra < N) g_hh[(size_t)ra * 32 + hidx] = __floats2half2_rn(d[ng][0], d[ng][1]);
        if (rb < N) g_hh[(size_t)rb * 32 + hidx] = __floats2half2_rn(d[ng][2], d[ng][3]);
    }
    #pragma unroll
    for (int o = 1; o < 4; o <<= 1) {
        sa  += __shfl_down_sync(0xFFFFFFFFu, sa,  o, 4);
        da  += __shfl_down_sync(0xFFFFFFFFu, da,  o, 4);
        sb_ += __shfl_down_sync(0xFFFFFFFFu, sb_, o, 4);
        db  += __shfl_down_sync(0xFFFFFFFFu, db,  o, 4);
    }
    if (tg == 0) {
        if (ra < N) { g_as[ra] = sa;  g_ad[ra] = da; }
        if (rb < N) { g_as[rb] = sb_; g_ad[rb] = db; }
    }
}

// ============================ scatter: src -> dst buckets (pure permutation) ============================
__global__ void k_scatter(const unsigned int* __restrict__ raw, int E) {
    int e = blockIdx.x * 256 + threadIdx.x;
    int is32 = __syncthreads_or((e < E) && (raw[2 * e + 1] != 0u));
    if (e >= E) return;
    int s, d;
    if (!is32) {
        const long long* p = (const long long*)raw;
        s = (int)p[e]; d = (int)p[E + e];
    } else {
        const int* p = (const int*)raw;
        s = p[e]; d = p[E + e];
    }
    int pos = atomicAdd(&g_cnt[d], 1);
    if (pos < CAP)
        g_eb[d * CAP + pos] = s;
}

// ============================ fused softmax + aggregate + ELU ============================
// One warp per node. Edge table (w, byte-offset) staged in smem; warp split
// into 2 edge-groups of 16 lanes, each lane owns 4 features (uint2 = 2 half2).
__global__ void k_fused(float* __restrict__ out, int N, float Ef) {
    __shared__ int2 tab[8][32];
    int wib = threadIdx.x >> 5;
    int node = (int)((blockIdx.x * blockDim.x + threadIdx.x) >> 5);
    int lane = threadIdx.x & 31;
    if (node >= N) return;
    int degc = g_cnt[node];
    int deg = min(degc, CAP);
    const int* buf = g_eb + node * CAP;
    float ad_node = g_ad[node];
    const char* hbase = (const char*)g_hh;

    int grp = lane >> 4;                     // edge group 0/1
    int fl  = lane & 15;                     // feature lane: bytes fl*8
    float a0 = 0.f, a1 = 0.f, a2 = 0.f, a3 = 0.f;

    if (deg <= 32) {
        // ---- register fast path: one edge per lane ----
        int s = (lane < deg) ? buf[lane] : 0;                 // coalesced 128B
        float l = (lane < deg) ? g_as[s] + ad_node : -3.0e38f;
        l = (l > 0.f) ? l : 0.2f * l;                          // leaky_relu
        float mm = l;
        #pragma unroll
        for (int o = 16; o; o >>= 1)
            mm = fmaxf(mm, __shfl_xor_sync(0xFFFFFFFFu, mm, o));
        float m = fmaxf(mm, 0.f);
        float el = (lane < deg) ? __expf(l - m) : 0.f;
        float sum = el;
        #pragma unroll
        for (int o = 16; o; o >>= 1)
            sum += __shfl_xor_sync(0xFFFFFFFFu, sum, o);
        float inv = 1.f / (sum + (Ef - (float)degc) * __expf(-m));
        tab[wib][lane] = make_int2(__float_as_int(el * inv), s * 128);
        __syncwarp();
        for (int j = grp; j < deg; j += 2) {
            int2 t = tab[wib][j];                              // LDS.64 broadcast
            float wj = __int_as_float(t.x);
            uint2 hv = *(const uint2*)(hbase + t.y + fl * 8);
            float2 f0 = __half22float2(*(const __half2*)&hv.x);
            float2 f1 = __half22float2(*(const __half2*)&hv.y);
            a0 += wj * f0.x; a1 += wj * f0.y;
            a2 += wj * f1.x; a3 += wj * f1.y;
        }
    } else {
        // ---- rare fallback (33..64 edges) ----
        float mm = -3.0e38f;
        for (int i = lane; i < deg; i += 32) {
            float l = g_as[buf[i]] + ad_node;
            l = (l > 0.f) ? l : 0.2f * l;
            mm = fmaxf(mm, l);
        }
        #pragma unroll
        for (int o = 16; o; o >>= 1)
            mm = fmaxf(mm, __shfl_xor_sync(0xFFFFFFFFu, mm, o));
        float m = fmaxf(mm, 0.f);
        float sum = 0.f;
        for (int i = lane; i < deg; i += 32) {
            float l = g_as[buf[i]] + ad_node;
            l = (l > 0.f) ? l : 0.2f * l;
            sum += __expf(l - m);
        }
        #pragma unroll
        for (int o = 16; o; o >>= 1)
            sum += __shfl_xor_sync(0xFFFFFFFFu, sum, o);
        float inv = 1.f / (sum + (Ef - (float)degc) * __expf(-m));
        for (int j = grp; j < deg; j += 2) {
            int s = buf[j];                                    // broadcast (L1-hot)
            float l = g_as[s] + ad_node;
            l = (l > 0.f) ? l : 0.2f * l;
            float wj = __expf(l - m) * inv;
            uint2 hv = *(const uint2*)(hbase + s * 128 + fl * 8);
            float2 f0 = __half22float2(*(const __half2*)&hv.x);
            float2 f1 = __half22float2(*(const __half2*)&hv.y);
            a0 += wj * f0.x; a1 += wj * f0.y;
            a2 += wj * f1.x; a3 += wj * f1.y;
        }
    }

    // combine the two edge-groups, then lanes 0-15 write float4
    a0 += __shfl_down_sync(0xFFFFFFFFu, a0, 16);
    a1 += __shfl_down_sync(0xFFFFFFFFu, a1, 16);
    a2 += __shfl_down_sync(0xFFFFFFFFu, a2, 16);
    a3 += __shfl_down_sync(0xFFFFFFFFu, a3, 16);
    if (lane < 16) {
        a0 = (a0 > 0.f) ? a0 : expm1f(a0);
        a1 = (a1 > 0.f) ? a1 : expm1f(a1);
        a2 = (a2 > 0.f) ? a2 : expm1f(a2);
        a3 = (a3 > 0.f) ? a3 : expm1f(a3);
        *(float4*)&out[(size_t)node * F_OUT + fl * 4] = make_float4(a0, a1, a2, a3);
    }
}

// ---------------------------------------------------------------------------
extern "C" void kernel_launch(void* const* d_in, const int* in_sizes, int n_in,
                              void* d_out, int out_size) {
    int order[8];
    for (int i = 0; i < n_in; i++) order[i] = i;
    for (int i = 0; i < n_in; i++)
        for (int j = i + 1; j < n_in; j++)
            if (in_sizes[order[j]] > in_sizes[order[i]]) {
                int tmp = order[i]; order[i] = order[j]; order[j] = tmp;
            }
    const float* x   = (const float*)d_in[order[0]];
    const void*  ei  = (const void*) d_in[order[1]];
    const float* W   = (const float*)d_in[order[2]];
    const float* att = (const float*)d_in[order[3]];
    int N = in_sizes[order[0]] / F_IN;       // 50000
    int E = in_sizes[order[1]] / 2;          // 800000

    static int attr_done = 0;
    if (!attr_done) {
        cudaFuncSetAttribute(k_gemm_mma, cudaFuncAttributeMaxDynamicSharedMemorySize, SM_TOTAL);
        attr_done = 1;
    }

    int zblks = (N + 255) / 256;
    k_init    <<<zblks + WSPLIT_BLKS, 256>>>(W, N, zblks);
    k_gemm_mma<<<(N + TILE_M - 1) / TILE_M, 256, SM_TOTAL>>>(x, att, N);
    k_scatter <<<(E + 255) / 256, 256>>>((const unsigned int*)ei, E);
    k_fused   <<<((N * 32) + 255) / 256, 256>>>((float*)d_out, N, (float)E);
}

// round 14
// speedup vs baseline: 1.0429x; 1.0429x over previous
#include <cuda_runtime.h>
#include <cuda_bf16.h>
#include <cuda_fp16.h>
#include <cstdint>

#define NMAX 50000
#define EMAX 800000
#define F_IN 128
#define F_OUT 64
#define TILE_M 128
#define CAP 64                               // per-dst bucket capacity (max deg ~42)
#define WSPLIT_BLKS 32                       // 8192 / 256

// ---- device scratch (no allocations allowed) ----
__device__ __half2 g_hh[NMAX * 32];          // h in half2 (rows of 128 B)
__device__ float g_as[NMAX];                 // h . a1
__device__ float g_ad[NMAX];                 // h . a2
__device__ int   g_cnt[NMAX];                // per-dst cursor / degree
__device__ int2  g_eb[NMAX * CAP];           // (src*128, logit bits) buckets, 25.6MB
__device__ uint4 g_whi4[1024];               // W hi split, bf16 [128][64]
__device__ uint4 g_wlo4[1024];               // W lo split, bf16 [128][64]

// ============================ init: zero counters + W split ============================
__global__ void k_init(const float* __restrict__ W, int N, int zblks) {
    int b = blockIdx.x;
    int t = threadIdx.x;
    if (b < zblks) {
        int i = b * 256 + t;
        if (i < N) g_cnt[i] = 0;
    } else {
        int i = (b - zblks) * 256 + t;       // < 8192
        float w = W[i];
        __nv_bfloat16 hi = __float2bfloat16(w);
        __nv_bfloat16 lo = __float2bfloat16(w - __bfloat162float(hi));
        ((__nv_bfloat16*)g_whi4)[i] = hi;
        ((__nv_bfloat16*)g_wlo4)[i] = lo;
    }
}

// ============================ HMMA GEMM (A direct-from-gmem) + fused alpha ============================
#define PB_B 144
#define SM_B_HI 0
#define SM_B_LO (F_IN * PB_B)
#define SM_TOTAL (2 * F_IN * PB_B)           // 36 KB

__device__ __forceinline__ uint32_t smem_u32(const void* p) {
    uint32_t a;
    asm("{ .reg .u64 t; cvta.to.shared.u64 t, %1; cvt.u32.u64 %0, t; }" : "=r"(a) : "l"(p));
    return a;
}

__device__ __forceinline__ void split2(float a, float b, uint32_t& hi, uint32_t& lo) {
    __nv_bfloat16 ah = __float2bfloat16(a);
    __nv_bfloat16 bh = __float2bfloat16(b);
    __nv_bfloat16 al = __float2bfloat16(a - __bfloat162float(ah));
    __nv_bfloat16 bl = __float2bfloat16(b - __bfloat162float(bh));
    hi = (uint32_t)__bfloat16_as_ushort(ah) | ((uint32_t)__bfloat16_as_ushort(bh) << 16);
    lo = (uint32_t)__bfloat16_as_ushort(al) | ((uint32_t)__bfloat16_as_ushort(bl) << 16);
}

#define LDSM_X4T(r0, r1, r2, r3, addr) \
    asm volatile("ldmatrix.sync.aligned.m8n8.x4.trans.shared.b16 {%0,%1,%2,%3}, [%4];" \
                 : "=r"(r0), "=r"(r1), "=r"(r2), "=r"(r3) : "r"(addr))
#define MMA_BF16(d, a0, a1, a2, a3, b0, b1) \
    asm volatile("mma.sync.aligned.m16n8k16.row.col.f32.bf16.bf16.f32 " \
                 "{%0,%1,%2,%3}, {%4,%5,%6,%7}, {%8,%9}, {%0,%1,%2,%3};" \
                 : "+f"((d)[0]), "+f"((d)[1]), "+f"((d)[2]), "+f"((d)[3]) \
                 : "r"(a0), "r"(a1), "r"(a2), "r"(a3), "r"(b0), "r"(b1))

__global__ void __launch_bounds__(256, 3)
k_gemm_mma(const float* __restrict__ x, const float* __restrict__ att, int N) {
    extern __shared__ char smem[];
    uint32_t sb = smem_u32(smem);
    int tid = threadIdx.x;
    int wid = tid >> 5;
    int lane = tid & 31;
    int row0 = blockIdx.x * TILE_M;

    for (int i = tid; i < 1024; i += 256) {
        int k = i >> 3, c8 = i & 7;
        int off = k * PB_B + c8 * 16;
        *(uint4*)(smem + SM_B_HI + off) = g_whi4[i];
        *(uint4*)(smem + SM_B_LO + off) = g_wlo4[i];
    }
    __syncthreads();

    int lr = lane >> 2;
    int lc = lane & 3;
    int row_a = row0 + 16 * wid + lr;
    int row_b = row_a + 8;
    bool va = row_a < N, vb = row_b < N;
    const float* pa = x + (size_t)row_a * F_IN + lc * 2;
    const float* pb = x + (size_t)row_b * F_IN + lc * 2;

    int mi = lane >> 3;
    int wrow = lane & 7;
    uint32_t boff = (uint32_t)((wrow + (mi & 1) * 8) * PB_B + (mi >> 1) * 16);
    uint32_t bhi_base = sb + SM_B_HI + boff;
    uint32_t blo_base = sb + SM_B_LO + boff;

    float d[8][4];
    #pragma unroll
    for (int i = 0; i < 8; i++)
        #pragma unroll
        for (int j = 0; j < 4; j++) d[i][j] = 0.f;

    #pragma unroll
    for (int ks = 0; ks < 8; ks++) {
        float2 z = make_float2(0.f, 0.f);
        float2 xa0 = va ? *(const float2*)(pa + ks * 16)     : z;
        float2 xa1 = va ? *(const float2*)(pa + ks * 16 + 8) : z;
        float2 xb0 = vb ? *(const float2*)(pb + ks * 16)     : z;
        float2 xb1 = vb ? *(const float2*)(pb + ks * 16 + 8) : z;
        uint32_t ah[4], al[4];
        split2(xa0.x, xa0.y, ah[0], al[0]);
        split2(xb0.x, xb0.y, ah[1], al[1]);
        split2(xa1.x, xa1.y, ah[2], al[2]);
        split2(xb1.x, xb1.y, ah[3], al[3]);

        uint32_t bk = ks * 16 * PB_B;
        #pragma unroll
        for (int np = 0; np < 4; np++) {
            uint32_t h0, h1, h2, h3, l0, l1, l2, l3;
            LDSM_X4T(h0, h1, h2, h3, bhi_base + bk + np * 32);
            LDSM_X4T(l0, l1, l2, l3, blo_base + bk + np * 32);
            MMA_BF16(d[2 * np], ah[0], ah[1], ah[2], ah[3], h0, h1);
            MMA_BF16(d[2 * np], ah[0], ah[1], ah[2], ah[3], l0, l1);
            MMA_BF16(d[2 * np], al[0], al[1], al[2], al[3], h0, h1);
            MMA_BF16(d[2 * np + 1], ah[0], ah[1], ah[2], ah[3], h2, h3);
            MMA_BF16(d[2 * np + 1], ah[0], ah[1], ah[2], ah[3], l2, l3);
            MMA_BF16(d[2 * np + 1], al[0], al[1], al[2], al[3], h2, h3);
        }
    }

    // epilogue: h -> half2 + fused alpha dots
    int g = lane >> 2, tg = lane & 3;
    int ra = row0 + 16 * wid + g;
    int rb = ra + 8;
    float sa = 0.f, da = 0.f, sb_ = 0.f, db = 0.f;
    #pragma unroll
    for (int ng = 0; ng < 8; ng++) {
        int col = ng * 8 + tg * 2;
        float2 A1 = *(const float2*)&att[col];
        float2 A2 = *(const float2*)&att[F_OUT + col];
        sa  += d[ng][0] * A1.x + d[ng][1] * A1.y;
        da  += d[ng][0] * A2.x + d[ng][1] * A2.y;
        sb_ += d[ng][2] * A1.x + d[ng][3] * A1.y;
        db  += d[ng][2] * A2.x + d[ng][3] * A2.y;
        int hidx = ng * 4 + tg;
        if (ra < N) g_hh[(size_t)ra * 32 + hidx] = __floats2half2_rn(d[ng][0], d[ng][1]);
        if (rb < N) g_hh[(size_t)rb * 32 + hidx] = __floats2half2_rn(d[ng][2], d[ng][3]);
    }
    #pragma unroll
    for (int o = 1; o < 4; o <<= 1) {
        sa  += __shfl_down_sync(0xFFFFFFFFu, sa,  o, 4);
        da  += __shfl_down_sync(0xFFFFFFFFu, da,  o, 4);
        sb_ += __shfl_down_sync(0xFFFFFFFFu, sb_, o, 4);
        db  += __shfl_down_sync(0xFFFFFFFFu, db,  o, 4);
    }
    if (tg == 0) {
        if (ra < N) { g_as[ra] = sa;  g_ad[ra] = da; }
        if (rb < N) { g_as[rb] = sb_; g_ad[rb] = db; }
    }
}

// ============================ scatter: (src byte-off, logit) -> dst buckets ============================
__global__ void k_scatter(const unsigned int* __restrict__ raw, int E) {
    int e = blockIdx.x * 256 + threadIdx.x;
    int is32 = __syncthreads_or((e < E) && (raw[2 * e + 1] != 0u));
    if (e >= E) return;
    int s, d;
    if (!is32) {
        const long long* p = (const long long*)raw;
        s = (int)p[e]; d = (int)p[E + e];
    } else {
        const int* p = (const int*)raw;
        s = p[e]; d = p[E + e];
    }
    float l = g_as[s] + g_ad[d];
    l = (l > 0.f) ? l : 0.2f * l;            // leaky_relu(0.2)
    int pos = atomicAdd(&g_cnt[d], 1);
    if (pos < CAP)
        g_eb[d * CAP + pos] = make_int2(s * 128, __float_as_int(l));
}

// ============================ fused softmax + aggregate + ELU ============================
// One warp per node. (w, byte-off) staged in a 2KB smem table; inner loop:
// LDS.64 broadcast + LDG.32 gather + 2 CVT + 2 FFMA, unrolled x2.
__global__ void k_fused(float* __restrict__ out, int N, float Ef) {
    __shared__ int2 tab[8][32];
    int wib = threadIdx.x >> 5;
    int node = (int)((blockIdx.x * blockDim.x + threadIdx.x) >> 5);
    int lane = threadIdx.x & 31;
    if (node >= N) return;
    int degc = g_cnt[node];
    int deg = min(degc, CAP);
    const int2* buf = g_eb + node * CAP;
    const char* hlane = (const char*)g_hh + lane * 4;
    float ax = 0.f, ay = 0.f;

    if (deg <= 32) {
        // ---- register fast path: one edge per lane ----
        int2 ed = (lane < deg) ? buf[lane] : make_int2(0, 0);
        float l = (lane < deg) ? __int_as_float(ed.y) : -3.0e38f;
        float mm = l;
        #pragma unroll
        for (int o = 16; o; o >>= 1)
            mm = fmaxf(mm, __shfl_xor_sync(0xFFFFFFFFu, mm, o));
        float m = fmaxf(mm, 0.f);
        float el = (lane < deg) ? __expf(l - m) : 0.f;
        float sum = el;
        #pragma unroll
        for (int o = 16; o; o >>= 1)
            sum += __shfl_xor_sync(0xFFFFFFFFu, sum, o);
        float inv = 1.f / (sum + (Ef - (float)degc) * __expf(-m));
        tab[wib][lane] = make_int2(__float_as_int(el * inv), ed.x);
        __syncwarp();
        #pragma unroll 2
        for (int j = 0; j < deg; j++) {
            int2 t = tab[wib][j];                              // LDS.64 broadcast
            float wj = __int_as_float(t.x);
            float2 hv = __half22float2(*(const __half2*)(hlane + t.y));
            ax += wj * hv.x;
            ay += wj * hv.y;
        }
    } else {
        // ---- rare fallback (33..64 edges): memory loop ----
        float mm = -3.0e38f;
        for (int i = lane; i < deg; i += 32)
            mm = fmaxf(mm, __int_as_float(buf[i].y));
        #pragma unroll
        for (int o = 16; o; o >>= 1)
            mm = fmaxf(mm, __shfl_xor_sync(0xFFFFFFFFu, mm, o));
        float m = fmaxf(mm, 0.f);
        float sum = 0.f;
        for (int i = lane; i < deg; i += 32)
            sum += __expf(__int_as_float(buf[i].y) - m);
        #pragma unroll
        for (int o = 16; o; o >>= 1)
            sum += __shfl_xor_sync(0xFFFFFFFFu, sum, o);
        float inv = 1.f / (sum + (Ef - (float)degc) * __expf(-m));
        for (int j = 0; j < deg; j++) {
            int2 ed = buf[j];                                  // broadcast (L1-hot)
            float wj = __expf(__int_as_float(ed.y) - m) * inv;
            float2 hv = __half22float2(*(const __half2*)(hlane + ed.x));
            ax += wj * hv.x;
            ay += wj * hv.y;
        }
    }

    // ELU: expm1f is mandatory — (expf-1) loses all relative accuracy near 0
    ax = (ax > 0.f) ? ax : expm1f(ax);
    ay = (ay > 0.f) ? ay : expm1f(ay);
    *(float2*)&out[(size_t)node * F_OUT + lane * 2] = make_float2(ax, ay);
}

// ---------------------------------------------------------------------------
extern "C" void kernel_launch(void* const* d_in, const int* in_sizes, int n_in,
                              void* d_out, int out_size) {
    int order[8];
    for (int i = 0; i < n_in; i++) order[i] = i;
    for (int i = 0; i < n_in; i++)
        for (int j = i + 1; j < n_in; j++)
            if (in_sizes[order[j]] > in_sizes[order[i]]) {
                int tmp = order[i]; order[i] = order[j]; order[j] = tmp;
            }
    const float* x   = (const float*)d_in[order[0]];
    const void*  ei  = (const void*) d_in[order[1]];
    const float* W   = (const float*)d_in[order[2]];
    const float* att = (const float*)d_in[order[3]];
    int N = in_sizes[order[0]] / F_IN;       // 50000
    int E = in_sizes[order[1]] / 2;          // 800000

    static int attr_done = 0;
    if (!attr_done) {
        cudaFuncSetAttribute(k_gemm_mma, cudaFuncAttributeMaxDynamicSharedMemorySize, SM_TOTAL);
        attr_done = 1;
    }

    int zblks = (N + 255) / 256;
    k_init    <<<zblks + WSPLIT_BLKS, 256>>>(W, N, zblks);
    k_gemm_mma<<<(N + TILE_M - 1) / TILE_M, 256, SM_TOTAL>>>(x, att, N);
    k_scatter <<<(E + 255) / 256, 256>>>((const unsigned int*)ei, E);
    k_fused   <<<((N * 32) + 255) / 256, 256>>>((float*)d_out, N, (float)E);
}